// round 11
// baseline (speedup 1.0000x reference)
#include <cuda_runtime.h>
#include <cuda_fp16.h>
#include <math.h>

#define C   128
#define HW  1024
#define N   4096
#define K   128
#define INV_TEMP (1.0f/0.07f)

// Scratch: normalized row-major [N, C] fp16 features (1 MB each).
__device__ __align__(16) __half g_qh[N * C];
__device__ __align__(16) __half g_kh[N * C];

// One block per (tensor p, batch b, 32-wide hw chunk): 2*4*32 = 256 blocks.
__global__ void normalize_kernel(const float* __restrict__ fq,
                                 const float* __restrict__ fk,
                                 float* __restrict__ out) {
    __shared__ float s[C][33];
    __shared__ float ps[8][32];
    __shared__ float inv[32];

    if (blockIdx.x == 0 && threadIdx.x == 0) out[0] = 0.0f;

    const int p   = blockIdx.x >> 7;          // 0 = q, 1 = k
    const int b   = (blockIdx.x >> 5) & 3;
    const int hw0 = (blockIdx.x & 31) << 5;
    const int t   = threadIdx.x;

    const float* src = (p == 0 ? fq : fk) + (size_t)b * C * HW + hw0;

    #pragma unroll
    for (int iter = 0; iter < 16; iter++) {
        int e = t + iter * 256;
        int c = e >> 5, i = e & 31;
        s[c][i] = src[c * HW + i];
    }
    __syncthreads();

    {
        int i = t & 31, c0 = t >> 5;
        float acc = 0.0f;
        #pragma unroll
        for (int c = c0; c < C; c += 8) { float v = s[c][i]; acc += v * v; }
        ps[c0][i] = acc;
    }
    __syncthreads();
    if (t < 32) {
        float sum = 0.0f;
        #pragma unroll
        for (int r = 0; r < 8; r++) sum += ps[r][t];
        inv[t] = 1.0f / fmaxf(sqrtf(sum), 1e-12f);
    }
    __syncthreads();

    __half* dst = (p == 0 ? g_qh : g_kh) + ((size_t)b * HW + hw0) * C;
    #pragma unroll
    for (int iter = 0; iter < 16; iter++) {
        int e  = t + iter * 256;
        int ii = e >> 7, c = e & 127;
        dst[ii * C + c] = __float2half(s[c][ii] * inv[ii]);
    }
}

// Lane-local 16-element partial dot: one HFMA2 chain over 8 half2.
__device__ __forceinline__ float dot16h(const uint4& qv0, const uint4& qv1,
                                        const uint4& kv0, const uint4& kv1) {
    const __half2* q = reinterpret_cast<const __half2*>(&qv0);
    const __half2* Q = reinterpret_cast<const __half2*>(&qv1);
    const __half2* k = reinterpret_cast<const __half2*>(&kv0);
    const __half2* Kk = reinterpret_cast<const __half2*>(&kv1);
    __half2 acc = __hmul2(q[0], k[0]);
    acc = __hfma2(q[1], k[1], acc);
    acc = __hfma2(q[2], k[2], acc);
    acc = __hfma2(q[3], k[3], acc);
    acc = __hfma2(Q[0], Kk[0], acc);
    acc = __hfma2(Q[1], Kk[1], acc);
    acc = __hfma2(Q[2], Kk[2], acc);
    acc = __hfma2(Q[3], Kk[3], acc);
    const float2 f = __half22float2(acc);
    return f.x + f.y;
}

// 8-lane-group all-reduce on a fully converged warp: xor 4/2/1 stay inside
// the 8-lane group; every lane ends with its group's sum. Full mask.
__device__ __forceinline__ float group8_allsum(float p) {
    p += __shfl_xor_sync(0xffffffffu, p, 4);
    p += __shfl_xor_sync(0xffffffffu, p, 2);
    p += __shfl_xor_sync(0xffffffffu, p, 1);
    return p;
}

// Two warps per row. Slot table sidx[136]: slot 0 = positive (idx n),
// 1..128 = negatives, 129..135 = dummies (idx n, each contributes
// exp(lpos); subtracted analytically at the end -> branchless inner loop).
// Half 0: slots 0..71 (9 trips of 8). Half 1: slots 72..135 (8 trips).
// Online exp-sum (|logit| <= 1/0.07 -> fp32-exact, no max pass).
__global__ void pnce_kernel(const int* __restrict__ negi,
                            float* __restrict__ out) {
    __shared__ int   sidx[4][136];
    __shared__ float spart[4][2];

    const int t    = threadIdx.x;
    const int w    = t >> 5;
    const int lane = t & 31;
    const int pr   = w >> 1;        // row slot in block 0..3
    const int h    = w & 1;         // half 0/1
    const int g    = lane >> 3;     // group 0..3
    const int l8   = lane & 7;      // lane within group
    const int n    = (blockIdx.x << 2) + pr;

    // Each warp stages exactly the slots it will read (-> __syncwarp).
    if (h == 0) {
        sidx[pr][lane]      = (lane == 0) ? n : negi[n * K + lane - 1];
        sidx[pr][lane + 32] = negi[n * K + lane + 31];
        if (lane < 8) sidx[pr][lane + 64] = negi[n * K + lane + 63];
    } else {
        sidx[pr][lane + 72]  = negi[n * K + lane + 71];
        const int s2 = lane + 104;
        sidx[pr][s2] = (s2 <= 128) ? negi[n * K + s2 - 1] : n;
    }
    __syncwarp();

    const uint4* qptr = reinterpret_cast<const uint4*>(g_qh + (size_t)n * C);
    const uint4 qv0 = qptr[l8];
    const uint4 qv1 = qptr[l8 + 8];

    // Lane's byte base into the key table (+l8*16); row offset = idx << 8.
    const char* kb = reinterpret_cast<const char*>(g_kh) + l8 * 16;

    float s    = 0.0f;
    float lpos = 0.0f;              // set by half 0, group 0, trip 0 (SEL)

    const int sbase = h ? 72 : 0;
    const int trips = 9 - h;        // 9 or 8

    for (int T = 0; T < trips; T++) {
        const int s1 = sbase + T * 8 + g;
        const int i1 = sidx[pr][s1];
        const int i2 = sidx[pr][s1 + 4];

        const uint4* p1 =
            reinterpret_cast<const uint4*>(kb + ((size_t)(unsigned)i1 << 8));
        const uint4* p2 =
            reinterpret_cast<const uint4*>(kb + ((size_t)(unsigned)i2 << 8));
        const uint4 a0 = p1[0];
        const uint4 a1 = p1[8];     // +128 bytes
        const uint4 b0 = p2[0];
        const uint4 b1 = p2[8];

        const float d1 = group8_allsum(dot16h(qv0, qv1, a0, a1));
        const float d2 = group8_allsum(dot16h(qv0, qv1, b0, b1));

        const float l1 = d1 * INV_TEMP;
        const float l2 = d2 * INV_TEMP;
        s += __expf(l1) + __expf(l2);
        if (s1 == 0) lpos = l1;     // compiles to SEL; true once (h0,g0,T0)
    }

    // Cross-group combine (groups hold identical sums; each counted once).
    s += __shfl_xor_sync(0xffffffffu, s, 8);
    s += __shfl_xor_sync(0xffffffffu, s, 16);
    if (lane == 0) spart[pr][h] = s;
    __syncthreads();

    if (h == 0 && lane == 0) {
        // Remove the 7 dummy contributions (each bitwise == exp(lpos)).
        const float total = spart[pr][0] + spart[pr][1] - 7.0f * __expf(lpos);
        atomicAdd(out, (__logf(total) - lpos) * (1.0f / (float)N));
    }
}

extern "C" void kernel_launch(void* const* d_in, const int* in_sizes, int n_in,
                              void* d_out, int out_size) {
    const float* feat_q = (const float*)d_in[0];
    const float* feat_k = (const float*)d_in[1];
    const int*   negi   = (const int*)d_in[2];
    float*       out    = (float*)d_out;

    normalize_kernel<<<256, 256>>>(feat_q, feat_k, out);
    pnce_kernel<<<N / 4, 256>>>(negi, out);
}